// round 8
// baseline (speedup 1.0000x reference)
#include <cuda_runtime.h>
#include <cuda_bf16.h>
#include <cuda_fp16.h>
#include <cuda_fp8.h>
#include <cstdint>

// Problem constants
#define VOCAB  128
#define EDIM   64
#define HDIM   256
#define TLEN   128
#define BATCH  8192
#define NOUT   16384   // VOCAB * TLEN
#define STEPS  15

// true spike limit is 1/(1-0.7^15) ~= 1.00477; use 0.9 for cross-numerics slack
#define LIM_SAFE 0.9f
#define P_SCALE    128.0f
#define P_INVSCALE (1.0f / 128.0f)

// ---------------- scratch (static device globals; no allocation) -------------
__device__ __align__(16) unsigned char g_P[TLEN * VOCAB * HDIM];  // 4 MB fp8 P[t,v,h]*128
__device__ float         g_x[BATCH * HDIM];              // 8 MB: input projection
__device__ unsigned      g_sbits[BATCH * 8];             // final-layer spike bits
__device__ float         g_thresh2;                      // (min_j (LIM-b0[j])/||W0[j]||)^2
__device__ int           g_bias_ok;                      // biases below limit & thresh>0
__device__ int           g_notsafe;                      // 1 = some row violates cert

// fp8x2 (16 bits) -> half2
__device__ __forceinline__ __half2 fp8x2_to_half2(unsigned short v) {
    unsigned r;
    asm("cvt.rn.f16x2.e4m3x2 %0, %1;" : "=r"(r) : "h"(v));
    return *(__half2*)&r;
}

// ---------------- certificate precompute (1 block, runs first, tiny) ---------
// no-spike cert: for all b, ||x_b|| < min_j (LIM_SAFE - b0[j]) / ||W0[j]||
// (Cauchy-Schwarz on base = x @ W0^T + b0), plus layer-1 bias < LIM_SAFE.
__global__ void __launch_bounds__(256) k_wnorm(const float* __restrict__ lif_W,
                                               const float* __restrict__ lif_b) {
    __shared__ float red[256];
    __shared__ int   okred;
    const int j = threadIdx.x;
    if (j == 0) { okred = 1; g_notsafe = 0; }
    __syncthreads();
    float w2 = 0.f;
    const float4* row = (const float4*)(lif_W + (size_t)j * HDIM);
#pragma unroll
    for (int q = 0; q < 64; q++) {
        const float4 wv = row[q];
        w2 += wv.x * wv.x + wv.y * wv.y + wv.z * wv.z + wv.w * wv.w;
    }
    const float margin = LIM_SAFE - lif_b[j];
    float th = margin * rsqrtf(fmaxf(w2, 1e-30f));  // per-j threshold on ||x||
    if (margin <= 0.f || lif_b[HDIM + j] >= LIM_SAFE) atomicAnd(&okred, 0);
    red[j] = th;
    __syncthreads();
    for (int o = 128; o > 0; o >>= 1) {
        if (j < o) red[j] = fminf(red[j], red[j + o]);
        __syncthreads();
    }
    if (j == 0) {
        g_bias_ok = okred;
        const float t = fmaxf(red[0], 0.f);
        g_thresh2 = t * t;
    }
}

// ---------------- P[t,v,h] = dot(emb[v,:], in_W[h, t*64 : t*64+64]) ----------
// grid (TLEN, 2): each block handles 64 vocab rows for one t. Stores fp8*128.
__global__ void __launch_bounds__(256) k_buildP(const float* __restrict__ emb,
                                                const float* __restrict__ in_W) {
    __shared__ float emb_s[64 * EDIM];  // 16 KB
    __shared__ uint4 st4[128];          // 2 KB fp8 staging (8 vocab rows)
    const int t     = blockIdx.x;
    const int vbase = blockIdx.y * 64;
    const int j     = threadIdx.x;  // h
    for (int i = j; i < 64 * EDIM; i += 256) emb_s[i] = emb[vbase * EDIM + i];
    float4 w4[16];
    const float4* src = (const float4*)(in_W + (size_t)j * 8192 + t * 64);
#pragma unroll
    for (int q = 0; q < 16; q++) w4[q] = src[q];
    __syncthreads();

    unsigned char* st = (unsigned char*)st4;
    for (int vg = 0; vg < 64; vg += 8) {
#pragma unroll
        for (int v2 = 0; v2 < 8; v2++) {
            const float4* ev4 = (const float4*)(emb_s + (vg + v2) * EDIM);
            float p = 0.f;
#pragma unroll
            for (int q = 0; q < 16; q++) {
                const float4 e = ev4[q];
                p += e.x * w4[q].x + e.y * w4[q].y + e.z * w4[q].z + e.w * w4[q].w;
            }
            st[v2 * HDIM + j] = __nv_cvt_float_to_fp8(p * P_SCALE, __NV_SATFINITE, __NV_E4M3);
        }
        __syncthreads();
        if (j < 128)
            ((uint4*)(g_P + (size_t)((t << 7) + vbase + vg) * HDIM))[j] = st4[j];
        __syncthreads();
    }
}

// ---------------- k_mega: fill role + gather role in ONE kernel --------------
// Blocks [0, FILLBLK): bias broadcast out[b,:] = out_b (DRAM-write-bound).
// Blocks [FILLBLK, FILLBLK+GATHBLK): x-gather (L2-read-bound).
// Single kernel => roles are co-resident on every SM; overlap is structural.
#define OROWS   32
#define BTILES  (BATCH / OROWS)         // 256 batch tiles
#define FILLBLK 512
#define GATHBLK (BATCH / 8)             // 1024
__global__ void __launch_bounds__(256) k_mega(const int*   __restrict__ ids,
                                              const float* __restrict__ in_b,
                                              const float* __restrict__ out_b,
                                              float*       __restrict__ out) {
    if (blockIdx.x < FILLBLK) {
        // ---------------- fill role ----------------
        const int i = threadIdx.x;
        const int nbase = (blockIdx.x & 3) * 4096;
        float4 bias[4];
#pragma unroll
        for (int u = 0; u < 4; u++)
            bias[u] = *(const float4*)(out_b + nbase + (u * 256 + i) * 4);

        for (int bt = (blockIdx.x >> 2); bt < BTILES; bt += (FILLBLK >> 2)) {
            const int b0 = bt * OROWS;
#pragma unroll 4
            for (int r = 0; r < OROWS; r++) {
                float* dst = out + (size_t)(b0 + r) * NOUT + nbase;
#pragma unroll
                for (int u = 0; u < 4; u++)
                    __stcs((float4*)(dst + (u * 256 + i) * 4), bias[u]);
            }
        }
        return;
    }

    // ---------------- gather role ----------------
    __shared__ int ids_s[8][TLEN];
    const int lane = threadIdx.x & 31;
    const int w    = threadIdx.x >> 5;
    const int b    = (blockIdx.x - FILLBLK) * 8 + w;

    for (int i = lane; i < TLEN; i += 32) ids_s[w][i] = ids[b * TLEN + i];
    __syncwarp();

    __half2 a0 = __float2half2_rn(0.f);
    __half2 a1 = a0, a2 = a0, a3 = a0;

    const ushort4* Pb = (const ushort4*)g_P;  // 32 ushort4 per (t,v) row
#pragma unroll 4
    for (int t = 0; t < TLEN; t++) {
        const int id = ids_s[w][t];
        const ushort4 p = Pb[(size_t)((t << 7) + id) * 32 + lane];
        a0 = __hadd2(a0, fp8x2_to_half2(p.x));
        a1 = __hadd2(a1, fp8x2_to_half2(p.y));
        a2 = __hadd2(a2, fp8x2_to_half2(p.z));
        a3 = __hadd2(a3, fp8x2_to_half2(p.w));
    }

    float v[8];
    {
        float2 f0 = __half22float2(a0);
        float2 f1 = __half22float2(a1);
        float2 f2 = __half22float2(a2);
        float2 f3 = __half22float2(a3);
        v[0] = f0.x; v[1] = f0.y; v[2] = f1.x; v[3] = f1.y;
        v[4] = f2.x; v[5] = f2.y; v[6] = f3.x; v[7] = f3.y;
    }
    const float4 b0 = *(const float4*)(in_b + lane * 8);
    const float4 b1 = *(const float4*)(in_b + lane * 8 + 4);
    v[0] = v[0] * P_INVSCALE + b0.x; v[1] = v[1] * P_INVSCALE + b0.y;
    v[2] = v[2] * P_INVSCALE + b0.z; v[3] = v[3] * P_INVSCALE + b0.w;
    v[4] = v[4] * P_INVSCALE + b1.x; v[5] = v[5] * P_INVSCALE + b1.y;
    v[6] = v[6] * P_INVSCALE + b1.z; v[7] = v[7] * P_INVSCALE + b1.w;

    float* dst = g_x + (size_t)b * HDIM + lane * 8;
    *(float4*)(dst + 0) = make_float4(v[0], v[1], v[2], v[3]);
    *(float4*)(dst + 4) = make_float4(v[4], v[5], v[6], v[7]);

    float ns = 0.f;
#pragma unroll
    for (int i = 0; i < 8; i++) ns += v[i] * v[i];
#pragma unroll
    for (int o = 16; o > 0; o >>= 1) ns += __shfl_xor_sync(0xffffffffu, ns, o);
    if (lane == 0 && ns >= g_thresh2) g_notsafe = 1;
}

// ---------------- fused LIF recurrence (fallback only; 16 rows per block) ----
#define ROWS 16
__global__ void __launch_bounds__(256) k_lif(const float* __restrict__ lif_W,
                                             const float* __restrict__ rec_W,
                                             const float* __restrict__ lif_b) {
    if (g_bias_ok && !g_notsafe) return;  // certificate holds: no spikes

    __shared__ float    x_s[ROWS * HDIM];     // 16 KB
    __shared__ unsigned s0b[ROWS][8];
    __shared__ unsigned s1b[ROWS][8];
    __shared__ unsigned u0[8], u1[8];
    __shared__ int any0s, any1s;

    const int j    = threadIdx.x;
    const int lane = j & 31;
    const int wi   = j >> 5;
    const int b0   = blockIdx.x * ROWS;

    for (int i = j; i < ROWS * HDIM; i += 256) x_s[i] = g_x[b0 * HDIM + i];
    if (j < ROWS * 8) { s0b[j >> 3][j & 7] = 0u; s1b[j >> 3][j & 7] = 0u; }
    if (j < 8) { u0[j] = 0u; u1[j] = 0u; }
    if (j == 0) { any0s = 0; any1s = 0; }
    __syncthreads();

    // base[r] = x[r,:] @ lif_W0[j,:] + lif_b0[j]  (step-invariant)
    float base[ROWS];
#pragma unroll
    for (int r = 0; r < ROWS; r++) base[r] = 0.f;
    const float4* w0row = (const float4*)(lif_W + (size_t)j * HDIM);
    for (int k = 0; k < HDIM; k += 4) {
        const float4 wv = w0row[k >> 2];
#pragma unroll
        for (int r = 0; r < ROWS; r++) {
            const float4 xv = *(const float4*)&x_s[r * HDIM + k];
            base[r] += xv.x * wv.x + xv.y * wv.y + xv.z * wv.z + xv.w * wv.w;
        }
    }
    const float bj0 = lif_b[j];
    const float bj1 = lif_b[HDIM + j];
#pragma unroll
    for (int r = 0; r < ROWS; r++) base[r] += bj0;

    const float* LW1 = lif_W + (size_t)HDIM * HDIM + (size_t)j * HDIM;
    const float* RW0 = rec_W + (size_t)j * HDIM;
    const float* RW1 = rec_W + (size_t)HDIM * HDIM + (size_t)j * HDIM;

    float v0[ROWS], v1[ROWS];
#pragma unroll
    for (int r = 0; r < ROWS; r++) { v0[r] = 0.f; v1[r] = 0.f; }

    for (int step = 0; step < STEPS; step++) {
        // ======== layer 0 ========
        float cur[ROWS];
#pragma unroll
        for (int r = 0; r < ROWS; r++) cur[r] = base[r];
        if (any0s) {
            for (int k = 0; k < HDIM; k++) {
                const unsigned bit = 1u << (k & 31);
                const int wk = k >> 5;
                if (u0[wk] & bit) {
                    float wv = RW0[k];
#pragma unroll
                    for (int r = 0; r < ROWS; r++)
                        if (s0b[r][wk] & bit) cur[r] += wv;
                }
            }
        }
        unsigned spmask = 0u;
#pragma unroll
        for (int r = 0; r < ROWS; r++) {
            v0[r] = 0.7f * v0[r] + 0.3f * cur[r];
            if (v0[r] >= 1.0f) { spmask |= (1u << r); v0[r] = 0.f; }
        }
        __syncthreads();
#pragma unroll
        for (int r = 0; r < ROWS; r++) {
            unsigned bal = __ballot_sync(0xffffffffu, (spmask >> r) & 1u);
            if (lane == 0) s0b[r][wi] = bal;
        }
        __syncthreads();
        if (j < 8) {
            unsigned o = 0;
#pragma unroll
            for (int r = 0; r < ROWS; r++) o |= s0b[r][j];
            u0[j] = o;
        }
        __syncthreads();
        if (j == 0)
            any0s = (u0[0] | u0[1] | u0[2] | u0[3] | u0[4] | u0[5] | u0[6] | u0[7]) ? 1 : 0;
        __syncthreads();

        // ======== layer 1 (input = NEW layer-0 spikes) ========
#pragma unroll
        for (int r = 0; r < ROWS; r++) cur[r] = bj1;
        if (any0s) {
            for (int k = 0; k < HDIM; k++) {
                const unsigned bit = 1u << (k & 31);
                const int wk = k >> 5;
                if (u0[wk] & bit) {
                    float wv = LW1[k];
#pragma unroll
                    for (int r = 0; r < ROWS; r++)
                        if (s0b[r][wk] & bit) cur[r] += wv;
                }
            }
        }
        if (any1s) {
            for (int k = 0; k < HDIM; k++) {
                const unsigned bit = 1u << (k & 31);
                const int wk = k >> 5;
                if (u1[wk] & bit) {
                    float wv = RW1[k];
#pragma unroll
                    for (int r = 0; r < ROWS; r++)
                        if (s1b[r][wk] & bit) cur[r] += wv;
                }
            }
        }
        spmask = 0u;
#pragma unroll
        for (int r = 0; r < ROWS; r++) {
            v1[r] = 0.7f * v1[r] + 0.3f * cur[r];
            if (v1[r] >= 1.0f) { spmask |= (1u << r); v1[r] = 0.f; }
        }
        __syncthreads();
#pragma unroll
        for (int r = 0; r < ROWS; r++) {
            unsigned bal = __ballot_sync(0xffffffffu, (spmask >> r) & 1u);
            if (lane == 0) s1b[r][wi] = bal;
        }
        __syncthreads();
        if (j < 8) {
            unsigned o = 0;
#pragma unroll
            for (int r = 0; r < ROWS; r++) o |= s1b[r][j];
            u1[j] = o;
        }
        __syncthreads();
        if (j == 0)
            any1s = (u1[0] | u1[1] | u1[2] | u1[3] | u1[4] | u1[5] | u1[6] | u1[7]) ? 1 : 0;
        __syncthreads();
    }

    if (j < ROWS * 8)
        g_sbits[(b0 + (j >> 3)) * 8 + (j & 7)] = s1b[j >> 3][j & 7];
}

// ---------------- k_fix: add spike contributions (no-op when certificate holds)
__global__ void __launch_bounds__(256) k_fix(const float* __restrict__ out_W,
                                             float* __restrict__ out) {
    if (g_bias_ok && !g_notsafe) return;
    __shared__ unsigned sb[32][8];
    const int i  = threadIdx.x;
    const int b0 = blockIdx.x * 32;
    sb[i >> 3][i & 7] = g_sbits[b0 * 8 + i];
    __syncthreads();
    unsigned any = 0;
#pragma unroll
    for (int r = 0; r < 32; r++)
#pragma unroll
        for (int w = 0; w < 8; w++) any |= sb[r][w];
    if (!any) return;

    // rare exact path
    for (int r = 0; r < 32; r++) {
        float* dst = out + (size_t)(b0 + r) * NOUT;
#pragma unroll
        for (int w = 0; w < 8; w++) {
            unsigned m = sb[r][w];
            while (m) {
                int k = (w << 5) + __ffs(m) - 1;
                m &= m - 1;
                for (int c = i; c < NOUT; c += 256)
                    dst[c] += out_W[(size_t)c * HDIM + k];
            }
        }
    }
}

// ---------------- launch ------------------------------------------------------
extern "C" void kernel_launch(void* const* d_in, const int* in_sizes, int n_in,
                              void* d_out, int out_size) {
    const int*   ids   = (const int*)d_in[0];
    const float* emb   = (const float*)d_in[1];
    const float* in_W  = (const float*)d_in[2];
    const float* in_b  = (const float*)d_in[3];
    const float* lif_W = (const float*)d_in[4];
    const float* lif_b = (const float*)d_in[5];
    const float* rec_W = (const float*)d_in[6];
    const float* out_W = (const float*)d_in[7];
    const float* out_b = (const float*)d_in[8];
    float* out = (float*)d_out;

    k_wnorm<<<1, 256>>>(lif_W, lif_b);
    k_buildP<<<dim3(TLEN, 2), 256>>>(emb, in_W);
    k_mega<<<FILLBLK + GATHBLK, 256>>>(ids, in_b, out_b, out);
    k_lif<<<BATCH / ROWS, 256>>>(lif_W, rec_W, lif_b);
    k_fix<<<BATCH / 32, 256>>>(out_W, out);
}

// round 10
// speedup vs baseline: 1.0303x; 1.0303x over previous
#include <cuda_runtime.h>
#include <cuda_bf16.h>
#include <cuda_fp16.h>
#include <cuda_fp8.h>
#include <cstdint>

// Problem constants
#define VOCAB  128
#define EDIM   64
#define HDIM   256
#define TLEN   128
#define BATCH  8192
#define NOUT   16384   // VOCAB * TLEN
#define STEPS  15

// true spike limit is 1/(1-0.7^15) ~= 1.00477; use 0.9 for cross-numerics slack
#define LIM_SAFE 0.9f
#define P_SCALE    128.0f
#define P_INVSCALE (1.0f / 128.0f)

// ---------------- scratch (static device globals; no allocation) -------------
__device__ __align__(16) unsigned char g_P[TLEN * VOCAB * HDIM];  // 4 MB fp8 P[t,v,h]*128
__device__ float         g_x[BATCH * HDIM];              // 8 MB: input projection
__device__ float         g_thresh2;                      // (min_j (LIM-b0[j])/||W0[j]||)^2
__device__ int           g_bias_ok;                      // biases below limit & thresh>0
__device__ int           g_notsafe;                      // 1 = some row violates cert

// fp8x2 (16 bits) -> half2
__device__ __forceinline__ __half2 fp8x2_to_half2(unsigned short v) {
    unsigned r;
    asm("cvt.rn.f16x2.e4m3x2 %0, %1;" : "=r"(r) : "h"(v));
    return *(__half2*)&r;
}

// L2 evict_last access policy: keeps P hot in L2 against the concurrent
// 536 MB fill write stream (which uses evict-first .cs stores).
__device__ __forceinline__ uint64_t mk_evict_last() {
    uint64_t pol;
    asm("createpolicy.fractional.L2::evict_last.b64 %0, 1.0;" : "=l"(pol));
    return pol;
}
__device__ __forceinline__ ushort4 ldg_P_hot(const ushort4* p, uint64_t pol) {
    ushort4 r;
    asm volatile("ld.global.nc.L2::cache_hint.v4.u16 {%0,%1,%2,%3}, [%4], %5;"
                 : "=h"(r.x), "=h"(r.y), "=h"(r.z), "=h"(r.w)
                 : "l"(p), "l"(pol));
    return r;
}
__device__ __forceinline__ void stg_P_hot(uint4* p, uint4 v, uint64_t pol) {
    asm volatile("st.global.L2::cache_hint.v4.b32 [%0], {%1,%2,%3,%4}, %5;"
                 :: "l"(p), "r"(v.x), "r"(v.y), "r"(v.z), "r"(v.w), "l"(pol)
                 : "memory");
}

// ---------------- certificate precompute (1 block, runs first, tiny) ---------
// no-spike cert: for all b, ||x_b|| < min_j (LIM_SAFE - b0[j]) / ||W0[j]||
// (Cauchy-Schwarz on base = x @ W0^T + b0), plus layer-1 bias < LIM_SAFE.
__global__ void __launch_bounds__(256) k_wnorm(const float* __restrict__ lif_W,
                                               const float* __restrict__ lif_b) {
    __shared__ float red[256];
    __shared__ int   okred;
    const int j = threadIdx.x;
    if (j == 0) { okred = 1; g_notsafe = 0; }
    __syncthreads();
    float w2 = 0.f;
    const float4* row = (const float4*)(lif_W + (size_t)j * HDIM);
#pragma unroll
    for (int q = 0; q < 64; q++) {
        const float4 wv = row[q];
        w2 += wv.x * wv.x + wv.y * wv.y + wv.z * wv.z + wv.w * wv.w;
    }
    const float margin = LIM_SAFE - lif_b[j];
    float th = margin * rsqrtf(fmaxf(w2, 1e-30f));  // per-j threshold on ||x||
    if (margin <= 0.f || lif_b[HDIM + j] >= LIM_SAFE) atomicAnd(&okred, 0);
    red[j] = th;
    __syncthreads();
    for (int o = 128; o > 0; o >>= 1) {
        if (j < o) red[j] = fminf(red[j], red[j + o]);
        __syncthreads();
    }
    if (j == 0) {
        g_bias_ok = okred;
        const float t = fmaxf(red[0], 0.f);
        g_thresh2 = t * t;
    }
}

// ---------------- P[t,v,h] = dot(emb[v,:], in_W[h, t*64 : t*64+64]) ----------
// grid (TLEN, 2): each block handles 64 vocab rows for one t. Stores fp8*128
// with evict_last so P starts (and stays) hot in L2.
__global__ void __launch_bounds__(256) k_buildP(const float* __restrict__ emb,
                                                const float* __restrict__ in_W) {
    __shared__ float emb_s[64 * EDIM];  // 16 KB
    __shared__ uint4 st4[128];          // 2 KB fp8 staging (8 vocab rows)
    const int t     = blockIdx.x;
    const int vbase = blockIdx.y * 64;
    const int j     = threadIdx.x;  // h
    const uint64_t pol = mk_evict_last();
    for (int i = j; i < 64 * EDIM; i += 256) emb_s[i] = emb[vbase * EDIM + i];
    float4 w4[16];
    const float4* src = (const float4*)(in_W + (size_t)j * 8192 + t * 64);
#pragma unroll
    for (int q = 0; q < 16; q++) w4[q] = src[q];
    __syncthreads();

    unsigned char* st = (unsigned char*)st4;
    for (int vg = 0; vg < 64; vg += 8) {
#pragma unroll
        for (int v2 = 0; v2 < 8; v2++) {
            const float4* ev4 = (const float4*)(emb_s + (vg + v2) * EDIM);
            float p = 0.f;
#pragma unroll
            for (int q = 0; q < 16; q++) {
                const float4 e = ev4[q];
                p += e.x * w4[q].x + e.y * w4[q].y + e.z * w4[q].z + e.w * w4[q].w;
            }
            st[v2 * HDIM + j] = __nv_cvt_float_to_fp8(p * P_SCALE, __NV_SATFINITE, __NV_E4M3);
        }
        __syncthreads();
        if (j < 128)
            stg_P_hot(((uint4*)(g_P + (size_t)((t << 7) + vbase + vg) * HDIM)) + j,
                      st4[j], pol);
        __syncthreads();
    }
}

// ---------------- k_mega: gather role + fill role in ONE kernel --------------
// Blocks [0, GATHBLK): x-gather (L2-read-bound, P pinned via evict_last).
// Blocks [GATHBLK, GATHBLK+FILLBLK): bias broadcast (DRAM-write-bound, .cs).
// Gather dispatches first so the P-critical phase sees minimal write pressure.
#define OROWS   32
#define BTILES  (BATCH / OROWS)         // 256 batch tiles
#define FILLBLK 512
#define GATHBLK (BATCH / 8)             // 1024
__global__ void __launch_bounds__(256) k_mega(const int*   __restrict__ ids,
                                              const float* __restrict__ in_b,
                                              const float* __restrict__ out_b,
                                              float*       __restrict__ out) {
    if (blockIdx.x >= GATHBLK) {
        // ---------------- fill role ----------------
        const int fb = blockIdx.x - GATHBLK;
        const int i = threadIdx.x;
        const int nbase = (fb & 3) * 4096;
        float4 bias[4];
#pragma unroll
        for (int u = 0; u < 4; u++)
            bias[u] = *(const float4*)(out_b + nbase + (u * 256 + i) * 4);

        for (int bt = (fb >> 2); bt < BTILES; bt += (FILLBLK >> 2)) {
            const int b0 = bt * OROWS;
#pragma unroll 4
            for (int r = 0; r < OROWS; r++) {
                float* dst = out + (size_t)(b0 + r) * NOUT + nbase;
#pragma unroll
                for (int u = 0; u < 4; u++)
                    __stcs((float4*)(dst + (u * 256 + i) * 4), bias[u]);
            }
        }
        return;
    }

    // ---------------- gather role ----------------
    __shared__ int ids_s[8][TLEN];
    const int lane = threadIdx.x & 31;
    const int w    = threadIdx.x >> 5;
    const int b    = blockIdx.x * 8 + w;
    const uint64_t pol = mk_evict_last();

    for (int i = lane; i < TLEN; i += 32) ids_s[w][i] = ids[b * TLEN + i];
    __syncwarp();

    __half2 a0 = __float2half2_rn(0.f);
    __half2 a1 = a0, a2 = a0, a3 = a0;

    const ushort4* Pb = (const ushort4*)g_P;  // 32 ushort4 per (t,v) row
#pragma unroll 4
    for (int t = 0; t < TLEN; t++) {
        const int id = ids_s[w][t];
        const ushort4 p = ldg_P_hot(Pb + (size_t)((t << 7) + id) * 32 + lane, pol);
        a0 = __hadd2(a0, fp8x2_to_half2(p.x));
        a1 = __hadd2(a1, fp8x2_to_half2(p.y));
        a2 = __hadd2(a2, fp8x2_to_half2(p.z));
        a3 = __hadd2(a3, fp8x2_to_half2(p.w));
    }

    float v[8];
    {
        float2 f0 = __half22float2(a0);
        float2 f1 = __half22float2(a1);
        float2 f2 = __half22float2(a2);
        float2 f3 = __half22float2(a3);
        v[0] = f0.x; v[1] = f0.y; v[2] = f1.x; v[3] = f1.y;
        v[4] = f2.x; v[5] = f2.y; v[6] = f3.x; v[7] = f3.y;
    }
    const float4 b0 = *(const float4*)(in_b + lane * 8);
    const float4 b1 = *(const float4*)(in_b + lane * 8 + 4);
    v[0] = v[0] * P_INVSCALE + b0.x; v[1] = v[1] * P_INVSCALE + b0.y;
    v[2] = v[2] * P_INVSCALE + b0.z; v[3] = v[3] * P_INVSCALE + b0.w;
    v[4] = v[4] * P_INVSCALE + b1.x; v[5] = v[5] * P_INVSCALE + b1.y;
    v[6] = v[6] * P_INVSCALE + b1.z; v[7] = v[7] * P_INVSCALE + b1.w;

    float* dst = g_x + (size_t)b * HDIM + lane * 8;
    __stcs((float4*)(dst + 0), make_float4(v[0], v[1], v[2], v[3]));
    __stcs((float4*)(dst + 4), make_float4(v[4], v[5], v[6], v[7]));

    float ns = 0.f;
#pragma unroll
    for (int i = 0; i < 8; i++) ns += v[i] * v[i];
#pragma unroll
    for (int o = 16; o > 0; o >>= 1) ns += __shfl_xor_sync(0xffffffffu, ns, o);
    if (lane == 0 && ns >= g_thresh2) g_notsafe = 1;
}

// ---------------- k_post: fused LIF fallback + output correction -------------
// Fast path (certificate holds): immediate return. Otherwise: exact 15-step
// LIF for 16 batch rows, then add out_W columns for fired neurons.
#define ROWS 16
__global__ void __launch_bounds__(256) k_post(const float* __restrict__ lif_W,
                                              const float* __restrict__ rec_W,
                                              const float* __restrict__ lif_b,
                                              const float* __restrict__ out_W,
                                              float*       __restrict__ out) {
    if (g_bias_ok && !g_notsafe) return;  // certificate holds: no spikes

    __shared__ float    x_s[ROWS * HDIM];     // 16 KB
    __shared__ unsigned s0b[ROWS][8];
    __shared__ unsigned s1b[ROWS][8];
    __shared__ unsigned u0[8], u1[8];
    __shared__ int any0s, any1s;

    const int j    = threadIdx.x;
    const int lane = j & 31;
    const int wi   = j >> 5;
    const int b0   = blockIdx.x * ROWS;

    for (int i = j; i < ROWS * HDIM; i += 256) x_s[i] = g_x[b0 * HDIM + i];
    if (j < ROWS * 8) { s0b[j >> 3][j & 7] = 0u; s1b[j >> 3][j & 7] = 0u; }
    if (j < 8) { u0[j] = 0u; u1[j] = 0u; }
    if (j == 0) { any0s = 0; any1s = 0; }
    __syncthreads();

    // base[r] = x[r,:] @ lif_W0[j,:] + lif_b0[j]  (step-invariant)
    float base[ROWS];
#pragma unroll
    for (int r = 0; r < ROWS; r++) base[r] = 0.f;
    const float4* w0row = (const float4*)(lif_W + (size_t)j * HDIM);
    for (int k = 0; k < HDIM; k += 4) {
        const float4 wv = w0row[k >> 2];
#pragma unroll
        for (int r = 0; r < ROWS; r++) {
            const float4 xv = *(const float4*)&x_s[r * HDIM + k];
            base[r] += xv.x * wv.x + xv.y * wv.y + xv.z * wv.z + xv.w * wv.w;
        }
    }
    const float bj0 = lif_b[j];
    const float bj1 = lif_b[HDIM + j];
#pragma unroll
    for (int r = 0; r < ROWS; r++) base[r] += bj0;

    const float* LW1 = lif_W + (size_t)HDIM * HDIM + (size_t)j * HDIM;
    const float* RW0 = rec_W + (size_t)j * HDIM;
    const float* RW1 = rec_W + (size_t)HDIM * HDIM + (size_t)j * HDIM;

    float v0[ROWS], v1[ROWS];
#pragma unroll
    for (int r = 0; r < ROWS; r++) { v0[r] = 0.f; v1[r] = 0.f; }

    for (int step = 0; step < STEPS; step++) {
        // ======== layer 0 ========
        float cur[ROWS];
#pragma unroll
        for (int r = 0; r < ROWS; r++) cur[r] = base[r];
        if (any0s) {
            for (int k = 0; k < HDIM; k++) {
                const unsigned bit = 1u << (k & 31);
                const int wk = k >> 5;
                if (u0[wk] & bit) {
                    float wv = RW0[k];
#pragma unroll
                    for (int r = 0; r < ROWS; r++)
                        if (s0b[r][wk] & bit) cur[r] += wv;
                }
            }
        }
        unsigned spmask = 0u;
#pragma unroll
        for (int r = 0; r < ROWS; r++) {
            v0[r] = 0.7f * v0[r] + 0.3f * cur[r];
            if (v0[r] >= 1.0f) { spmask |= (1u << r); v0[r] = 0.f; }
        }
        __syncthreads();
#pragma unroll
        for (int r = 0; r < ROWS; r++) {
            unsigned bal = __ballot_sync(0xffffffffu, (spmask >> r) & 1u);
            if (lane == 0) s0b[r][wi] = bal;
        }
        __syncthreads();
        if (j < 8) {
            unsigned o = 0;
#pragma unroll
            for (int r = 0; r < ROWS; r++) o |= s0b[r][j];
            u0[j] = o;
        }
        __syncthreads();
        if (j == 0)
            any0s = (u0[0] | u0[1] | u0[2] | u0[3] | u0[4] | u0[5] | u0[6] | u0[7]) ? 1 : 0;
        __syncthreads();

        // ======== layer 1 (input = NEW layer-0 spikes) ========
#pragma unroll
        for (int r = 0; r < ROWS; r++) cur[r] = bj1;
        if (any0s) {
            for (int k = 0; k < HDIM; k++) {
                const unsigned bit = 1u << (k & 31);
                const int wk = k >> 5;
                if (u0[wk] & bit) {
                    float wv = LW1[k];
#pragma unroll
                    for (int r = 0; r < ROWS; r++)
                        if (s0b[r][wk] & bit) cur[r] += wv;
                }
            }
        }
        if (any1s) {
            for (int k = 0; k < HDIM; k++) {
                const unsigned bit = 1u << (k & 31);
                const int wk = k >> 5;
                if (u1[wk] & bit) {
                    float wv = RW1[k];
#pragma unroll
                    for (int r = 0; r < ROWS; r++)
                        if (s1b[r][wk] & bit) cur[r] += wv;
                }
            }
        }
        spmask = 0u;
#pragma unroll
        for (int r = 0; r < ROWS; r++) {
            v1[r] = 0.7f * v1[r] + 0.3f * cur[r];
            if (v1[r] >= 1.0f) { spmask |= (1u << r); v1[r] = 0.f; }
        }
        __syncthreads();
#pragma unroll
        for (int r = 0; r < ROWS; r++) {
            unsigned bal = __ballot_sync(0xffffffffu, (spmask >> r) & 1u);
            if (lane == 0) s1b[r][wi] = bal;
        }
        __syncthreads();
        if (j < 8) {
            unsigned o = 0;
#pragma unroll
            for (int r = 0; r < ROWS; r++) o |= s1b[r][j];
            u1[j] = o;
        }
        __syncthreads();
        if (j == 0)
            any1s = (u1[0] | u1[1] | u1[2] | u1[3] | u1[4] | u1[5] | u1[6] | u1[7]) ? 1 : 0;
        __syncthreads();
    }

    // ---- apply corrections: out[b,:] += sum_{k fired} out_W[:,k] ----
    for (int r = 0; r < ROWS; r++) {
        unsigned any = 0;
#pragma unroll
        for (int w8 = 0; w8 < 8; w8++) any |= s1b[r][w8];
        if (!any) continue;
        float* dst = out + (size_t)(b0 + r) * NOUT;
#pragma unroll
        for (int w8 = 0; w8 < 8; w8++) {
            unsigned m = s1b[r][w8];
            while (m) {
                int k = (w8 << 5) + __ffs(m) - 1;
                m &= m - 1;
                for (int c = j; c < NOUT; c += 256)
                    dst[c] += out_W[(size_t)c * HDIM + k];
            }
        }
    }
}

// ---------------- launch ------------------------------------------------------
extern "C" void kernel_launch(void* const* d_in, const int* in_sizes, int n_in,
                              void* d_out, int out_size) {
    const int*   ids   = (const int*)d_in[0];
    const float* emb   = (const float*)d_in[1];
    const float* in_W  = (const float*)d_in[2];
    const float* in_b  = (const float*)d_in[3];
    const float* lif_W = (const float*)d_in[4];
    const float* lif_b = (const float*)d_in[5];
    const float* rec_W = (const float*)d_in[6];
    const float* out_W = (const float*)d_in[7];
    const float* out_b = (const float*)d_in[8];
    float* out = (float*)d_out;

    k_wnorm<<<1, 256>>>(lif_W, lif_b);
    k_buildP<<<dim3(TLEN, 2), 256>>>(emb, in_W);
    k_mega<<<GATHBLK + FILLBLK, 256>>>(ids, in_b, out_b, out);
    k_post<<<BATCH / ROWS, 256>>>(lif_W, rec_W, lif_b, out_W, out);
}

// round 11
// speedup vs baseline: 1.2555x; 1.2186x over previous
#include <cuda_runtime.h>
#include <cuda_bf16.h>
#include <cuda_fp16.h>
#include <cuda_fp8.h>
#include <cstdint>

// Problem constants
#define VOCAB  128
#define EDIM   64
#define HDIM   256
#define TLEN   128
#define BATCH  8192
#define NOUT   16384   // VOCAB * TLEN
#define STEPS  15

// true spike limit is 1/(1-0.7^15) ~= 1.00477; use 0.9 for cross-numerics slack
#define LIM_SAFE 0.9f
#define P_SCALE    128.0f
#define P_INVSCALE (1.0f / 128.0f)

// ---------------- scratch (static device globals; no allocation) -------------
__device__ __align__(16) unsigned char g_P[TLEN * VOCAB * HDIM];  // 4 MB fp8 P[t,v,h]*128
__device__ float         g_x[BATCH * HDIM];              // 8 MB: input projection
__device__ float         g_thresh2;                      // (min_j (LIM-b0[j])/||W0[j]||)^2
__device__ int           g_bias_ok;                      // biases below limit & thresh>0
__device__ int           g_notsafe;                      // 1 = some row violates cert

// fp8x2 (16 bits) -> half2
__device__ __forceinline__ __half2 fp8x2_to_half2(unsigned short v) {
    unsigned r;
    asm("cvt.rn.f16x2.e4m3x2 %0, %1;" : "=r"(r) : "h"(v));
    return *(__half2*)&r;
}

// ---------------- k_mega1: buildP + wnorm + fill roles in ONE kernel ---------
// Blocks [0,256):   buildP  (FMA-bound, tiny traffic -> co-runs with fill)
// Block  256:       wnorm   (certificate threshold precompute)
// Blocks [257,769): fill    (536 MB bias broadcast, DRAM-write-bound)
// buildP/wnorm dispatch first so they get wave-1 residency; they finish in
// ~12 us while fill streams for ~90 us. No L2 interference (disjoint traffic).
#define BP_BLOCKS 256
#define OROWS     32
#define BTILES    (BATCH / OROWS)        // 256 batch tiles
#define FILLBLK   512
#define MEGA1GRID (BP_BLOCKS + 1 + FILLBLK)
__global__ void __launch_bounds__(256) k_mega1(const float* __restrict__ emb,
                                               const float* __restrict__ in_W,
                                               const float* __restrict__ lif_W,
                                               const float* __restrict__ lif_b,
                                               const float* __restrict__ out_b,
                                               float*       __restrict__ out) {
    __shared__ __align__(16) char sm[16 * 1024 + 2 * 1024 + 32];
    const int bx = blockIdx.x;
    const int j  = threadIdx.x;

    if (bx < BP_BLOCKS) {
        // ---------------- buildP role ----------------
        // P[t,v,h] = dot(emb[v,:], in_W[h, t*64 : t*64+64]) stored fp8*128.
        float* emb_s = (float*)sm;                       // 16 KB: 64 vocab rows
        uint4* st4   = (uint4*)(sm + 16 * 1024);         // 2 KB fp8 staging
        const int t     = bx >> 1;
        const int vbase = (bx & 1) * 64;
        for (int i = j; i < 64 * EDIM; i += 256) emb_s[i] = emb[vbase * EDIM + i];
        float4 w4[16];
        const float4* src = (const float4*)(in_W + (size_t)j * 8192 + t * 64);
#pragma unroll
        for (int q = 0; q < 16; q++) w4[q] = src[q];
        __syncthreads();

        unsigned char* st = (unsigned char*)st4;
        for (int vg = 0; vg < 64; vg += 8) {
#pragma unroll
            for (int v2 = 0; v2 < 8; v2++) {
                const float4* ev4 = (const float4*)(emb_s + (vg + v2) * EDIM);
                float p = 0.f;
#pragma unroll
                for (int q = 0; q < 16; q++) {
                    const float4 e = ev4[q];
                    p += e.x * w4[q].x + e.y * w4[q].y + e.z * w4[q].z + e.w * w4[q].w;
                }
                st[v2 * HDIM + j] = __nv_cvt_float_to_fp8(p * P_SCALE, __NV_SATFINITE, __NV_E4M3);
            }
            __syncthreads();
            if (j < 128)
                ((uint4*)(g_P + (size_t)((t << 7) + vbase + vg) * HDIM))[j] = st4[j];
            __syncthreads();
        }
        return;
    }

    if (bx == BP_BLOCKS) {
        // ---------------- wnorm role ----------------
        // no-spike cert: for all b, ||x_b|| < min_j (LIM_SAFE - b0[j]) / ||W0[j]||
        // (Cauchy-Schwarz on base = x @ W0^T + b0), plus layer-1 bias < LIM_SAFE.
        float* red   = (float*)sm;
        int*   okred = (int*)(sm + 1024);
        if (j == 0) { *okred = 1; g_notsafe = 0; }
        __syncthreads();
        float w2 = 0.f;
        const float4* row = (const float4*)(lif_W + (size_t)j * HDIM);
#pragma unroll
        for (int q = 0; q < 64; q++) {
            const float4 wv = row[q];
            w2 += wv.x * wv.x + wv.y * wv.y + wv.z * wv.z + wv.w * wv.w;
        }
        const float margin = LIM_SAFE - lif_b[j];
        float th = margin * rsqrtf(fmaxf(w2, 1e-30f));
        if (margin <= 0.f || lif_b[HDIM + j] >= LIM_SAFE) atomicAnd(okred, 0);
        red[j] = th;
        __syncthreads();
        for (int o = 128; o > 0; o >>= 1) {
            if (j < o) red[j] = fminf(red[j], red[j + o]);
            __syncthreads();
        }
        if (j == 0) {
            g_bias_ok = *okred;
            const float t = fmaxf(red[0], 0.f);
            g_thresh2 = t * t;
        }
        return;
    }

    // ---------------- fill role ----------------
    const int fb = bx - (BP_BLOCKS + 1);
    const int nbase = (fb & 3) * 4096;
    float4 bias[4];
#pragma unroll
    for (int u = 0; u < 4; u++)
        bias[u] = *(const float4*)(out_b + nbase + (u * 256 + j) * 4);

    for (int bt = (fb >> 2); bt < BTILES; bt += (FILLBLK >> 2)) {
        const int b0 = bt * OROWS;
#pragma unroll 4
        for (int r = 0; r < OROWS; r++) {
            float* dst = out + (size_t)(b0 + r) * NOUT + nbase;
#pragma unroll
            for (int u = 0; u < 4; u++)
                __stcs((float4*)(dst + (u * 256 + j) * 4), bias[u]);
        }
    }
}

// ---------------- x[b,:] = in_b + (1/128) * sum_t P8[t, ids[b,t], :] ---------
// Runs serially after k_mega1 on an idle memory system: pure L2-read-bound
// (268 MB logical reads of the 4 MB P table at the LTS roofline).
__global__ void __launch_bounds__(256) k_gather(const int* __restrict__ ids,
                                                const float* __restrict__ in_b) {
    __shared__ int ids_s[8][TLEN];
    const int lane = threadIdx.x & 31;
    const int w    = threadIdx.x >> 5;
    const int b    = blockIdx.x * 8 + w;

    for (int i = lane; i < TLEN; i += 32) ids_s[w][i] = ids[b * TLEN + i];
    __syncwarp();

    __half2 a0 = __float2half2_rn(0.f);
    __half2 a1 = a0, a2 = a0, a3 = a0;

    const ushort4* Pb = (const ushort4*)g_P;  // 32 ushort4 per (t,v) row
#pragma unroll 4
    for (int t = 0; t < TLEN; t++) {
        const int id = ids_s[w][t];
        const ushort4 p = Pb[(size_t)((t << 7) + id) * 32 + lane];
        a0 = __hadd2(a0, fp8x2_to_half2(p.x));
        a1 = __hadd2(a1, fp8x2_to_half2(p.y));
        a2 = __hadd2(a2, fp8x2_to_half2(p.z));
        a3 = __hadd2(a3, fp8x2_to_half2(p.w));
    }

    float v[8];
    {
        float2 f0 = __half22float2(a0);
        float2 f1 = __half22float2(a1);
        float2 f2 = __half22float2(a2);
        float2 f3 = __half22float2(a3);
        v[0] = f0.x; v[1] = f0.y; v[2] = f1.x; v[3] = f1.y;
        v[4] = f2.x; v[5] = f2.y; v[6] = f3.x; v[7] = f3.y;
    }
    const float4 b0 = *(const float4*)(in_b + lane * 8);
    const float4 b1 = *(const float4*)(in_b + lane * 8 + 4);
    v[0] = v[0] * P_INVSCALE + b0.x; v[1] = v[1] * P_INVSCALE + b0.y;
    v[2] = v[2] * P_INVSCALE + b0.z; v[3] = v[3] * P_INVSCALE + b0.w;
    v[4] = v[4] * P_INVSCALE + b1.x; v[5] = v[5] * P_INVSCALE + b1.y;
    v[6] = v[6] * P_INVSCALE + b1.z; v[7] = v[7] * P_INVSCALE + b1.w;

    float* dst = g_x + (size_t)b * HDIM + lane * 8;
    __stcs((float4*)(dst + 0), make_float4(v[0], v[1], v[2], v[3]));
    __stcs((float4*)(dst + 4), make_float4(v[4], v[5], v[6], v[7]));

    float ns = 0.f;
#pragma unroll
    for (int i = 0; i < 8; i++) ns += v[i] * v[i];
#pragma unroll
    for (int o = 16; o > 0; o >>= 1) ns += __shfl_xor_sync(0xffffffffu, ns, o);
    if (lane == 0 && ns >= g_thresh2) g_notsafe = 1;
}

// ---------------- k_post: fused LIF fallback + output correction -------------
// Grid-strided with a small grid so the (always-taken) early exit costs ~1 us.
// Fallback: exact 15-step LIF for 16 rows/group, then add out_W columns.
#define ROWS 16
#define POSTBLK 128
__global__ void __launch_bounds__(256) k_post(const float* __restrict__ lif_W,
                                              const float* __restrict__ rec_W,
                                              const float* __restrict__ lif_b,
                                              const float* __restrict__ out_W,
                                              float*       __restrict__ out) {
    if (g_bias_ok && !g_notsafe) return;  // certificate holds: no spikes

    __shared__ float    x_s[ROWS * HDIM];     // 16 KB
    __shared__ unsigned s0b[ROWS][8];
    __shared__ unsigned s1b[ROWS][8];
    __shared__ unsigned u0[8], u1[8];
    __shared__ int any0s, any1s;

    const int j    = threadIdx.x;
    const int lane = j & 31;
    const int wi   = j >> 5;

    const float bj0 = lif_b[j];
    const float bj1 = lif_b[HDIM + j];
    const float* LW1 = lif_W + (size_t)HDIM * HDIM + (size_t)j * HDIM;
    const float* RW0 = rec_W + (size_t)j * HDIM;
    const float* RW1 = rec_W + (size_t)HDIM * HDIM + (size_t)j * HDIM;
    const float4* w0row = (const float4*)(lif_W + (size_t)j * HDIM);

    for (int grp = blockIdx.x; grp < BATCH / ROWS; grp += POSTBLK) {
        const int b0 = grp * ROWS;

        for (int i = j; i < ROWS * HDIM; i += 256) x_s[i] = g_x[b0 * HDIM + i];
        if (j < ROWS * 8) { s0b[j >> 3][j & 7] = 0u; s1b[j >> 3][j & 7] = 0u; }
        if (j < 8) { u0[j] = 0u; u1[j] = 0u; }
        if (j == 0) { any0s = 0; any1s = 0; }
        __syncthreads();

        // base[r] = x[r,:] @ lif_W0[j,:] + lif_b0[j]  (step-invariant)
        float base[ROWS];
#pragma unroll
        for (int r = 0; r < ROWS; r++) base[r] = 0.f;
        for (int k = 0; k < HDIM; k += 4) {
            const float4 wv = w0row[k >> 2];
#pragma unroll
            for (int r = 0; r < ROWS; r++) {
                const float4 xv = *(const float4*)&x_s[r * HDIM + k];
                base[r] += xv.x * wv.x + xv.y * wv.y + xv.z * wv.z + xv.w * wv.w;
            }
        }
#pragma unroll
        for (int r = 0; r < ROWS; r++) base[r] += bj0;

        float v0[ROWS], v1[ROWS];
#pragma unroll
        for (int r = 0; r < ROWS; r++) { v0[r] = 0.f; v1[r] = 0.f; }

        for (int step = 0; step < STEPS; step++) {
            // ======== layer 0 ========
            float cur[ROWS];
#pragma unroll
            for (int r = 0; r < ROWS; r++) cur[r] = base[r];
            if (any0s) {
                for (int k = 0; k < HDIM; k++) {
                    const unsigned bit = 1u << (k & 31);
                    const int wk = k >> 5;
                    if (u0[wk] & bit) {
                        float wv = RW0[k];
#pragma unroll
                        for (int r = 0; r < ROWS; r++)
                            if (s0b[r][wk] & bit) cur[r] += wv;
                    }
                }
            }
            unsigned spmask = 0u;
#pragma unroll
            for (int r = 0; r < ROWS; r++) {
                v0[r] = 0.7f * v0[r] + 0.3f * cur[r];
                if (v0[r] >= 1.0f) { spmask |= (1u << r); v0[r] = 0.f; }
            }
            __syncthreads();
#pragma unroll
            for (int r = 0; r < ROWS; r++) {
                unsigned bal = __ballot_sync(0xffffffffu, (spmask >> r) & 1u);
                if (lane == 0) s0b[r][wi] = bal;
            }
            __syncthreads();
            if (j < 8) {
                unsigned o = 0;
#pragma unroll
                for (int r = 0; r < ROWS; r++) o |= s0b[r][j];
                u0[j] = o;
            }
            __syncthreads();
            if (j == 0)
                any0s = (u0[0] | u0[1] | u0[2] | u0[3] | u0[4] | u0[5] | u0[6] | u0[7]) ? 1 : 0;
            __syncthreads();

            // ======== layer 1 (input = NEW layer-0 spikes) ========
#pragma unroll
            for (int r = 0; r < ROWS; r++) cur[r] = bj1;
            if (any0s) {
                for (int k = 0; k < HDIM; k++) {
                    const unsigned bit = 1u << (k & 31);
                    const int wk = k >> 5;
                    if (u0[wk] & bit) {
                        float wv = LW1[k];
#pragma unroll
                        for (int r = 0; r < ROWS; r++)
                            if (s0b[r][wk] & bit) cur[r] += wv;
                    }
                }
            }
            if (any1s) {
                for (int k = 0; k < HDIM; k++) {
                    const unsigned bit = 1u << (k & 31);
                    const int wk = k >> 5;
                    if (u1[wk] & bit) {
                        float wv = RW1[k];
#pragma unroll
                        for (int r = 0; r < ROWS; r++)
                            if (s1b[r][wk] & bit) cur[r] += wv;
                    }
                }
            }
            spmask = 0u;
#pragma unroll
            for (int r = 0; r < ROWS; r++) {
                v1[r] = 0.7f * v1[r] + 0.3f * cur[r];
                if (v1[r] >= 1.0f) { spmask |= (1u << r); v1[r] = 0.f; }
            }
            __syncthreads();
#pragma unroll
            for (int r = 0; r < ROWS; r++) {
                unsigned bal = __ballot_sync(0xffffffffu, (spmask >> r) & 1u);
                if (lane == 0) s1b[r][wi] = bal;
            }
            __syncthreads();
            if (j < 8) {
                unsigned o = 0;
#pragma unroll
                for (int r = 0; r < ROWS; r++) o |= s1b[r][j];
                u1[j] = o;
            }
            __syncthreads();
            if (j == 0)
                any1s = (u1[0] | u1[1] | u1[2] | u1[3] | u1[4] | u1[5] | u1[6] | u1[7]) ? 1 : 0;
            __syncthreads();
        }

        // ---- apply corrections: out[b,:] += sum_{k fired} out_W[:,k] ----
        for (int r = 0; r < ROWS; r++) {
            unsigned any = 0;
#pragma unroll
            for (int w8 = 0; w8 < 8; w8++) any |= s1b[r][w8];
            if (!any) continue;
            float* dst = out + (size_t)(b0 + r) * NOUT;
#pragma unroll
            for (int w8 = 0; w8 < 8; w8++) {
                unsigned m = s1b[r][w8];
                while (m) {
                    int k = (w8 << 5) + __ffs(m) - 1;
                    m &= m - 1;
                    for (int c = j; c < NOUT; c += 256)
                        dst[c] += out_W[(size_t)c * HDIM + k];
                }
            }
        }
        __syncthreads();  // smem reuse across grid-stride groups
    }
}

// ---------------- launch ------------------------------------------------------
extern "C" void kernel_launch(void* const* d_in, const int* in_sizes, int n_in,
                              void* d_out, int out_size) {
    const int*   ids   = (const int*)d_in[0];
    const float* emb   = (const float*)d_in[1];
    const float* in_W  = (const float*)d_in[2];
    const float* in_b  = (const float*)d_in[3];
    const float* lif_W = (const float*)d_in[4];
    const float* lif_b = (const float*)d_in[5];
    const float* rec_W = (const float*)d_in[6];
    const float* out_W = (const float*)d_in[7];
    const float* out_b = (const float*)d_in[8];
    float* out = (float*)d_out;

    k_mega1<<<MEGA1GRID, 256>>>(emb, in_W, lif_W, lif_b, out_b, out);
    k_gather<<<BATCH / 8, 256>>>(ids, in_b);
    k_post<<<POSTBLK, 256>>>(lif_W, rec_W, lif_b, out_W, out);
}